// round 4
// baseline (speedup 1.0000x reference)
#include <cuda_runtime.h>
#include <cuda_bf16.h>
#include <cuda_fp16.h>
#include <cstdint>

#define N_NODES 8192
#define N_EDGES 262144
#define D 512
#define MW 256   // 8192 bits / 32 = 256 mask words per row

// Scratch (device globals; no allocations allowed)
__device__ unsigned int g_mask[N_NODES * MW];                    // 8 MB adjacency bitmask
__device__ float        g_dinv[N_NODES];                         // D^{-1/2}
__device__ __align__(16) __half g_h[N_NODES * D];                // H' = dinv*(X@W), fp16
__device__ int          g_is64;                                  // edge_index dtype flag
__device__ __align__(16) __nv_bfloat16 g_xhi[N_NODES * D];       // bf16 split of X
__device__ __align__(16) __nv_bfloat16 g_xlo[N_NODES * D];
__device__ __align__(16) __nv_bfloat16 g_whi[D * D];             // bf16 split of W
__device__ __align__(16) __nv_bfloat16 g_wlo[D * D];

// ---------------------------------------------------------------------------
// 0) detect edge_index dtype (int64 vs int32)
// ---------------------------------------------------------------------------
__global__ void k_detect(const int* __restrict__ ei32) {
    int t = threadIdx.x;
    int nz = 0;
    #pragma unroll
    for (int i = t; i < 4096; i += 256) nz |= ei32[2 * i + 1];
    int any = __syncthreads_or(nz != 0);
    if (t == 0) g_is64 = any ? 0 : 1;
}

// ---------------------------------------------------------------------------
// 1) zero bitmask (vectorized)
// ---------------------------------------------------------------------------
__global__ void k_zero_mask() {
    int i = blockIdx.x * blockDim.x + threadIdx.x;
    if (i < N_NODES * MW / 4) ((uint4*)g_mask)[i] = make_uint4(0, 0, 0, 0);
}

// ---------------------------------------------------------------------------
// 2) symmetric edge scatter into bitmask (dedup for free)
// ---------------------------------------------------------------------------
__global__ void k_scatter(const void* __restrict__ ei_raw) {
    int e = blockIdx.x * blockDim.x + threadIdx.x;
    if (e >= N_EDGES) return;
    int u, v;
    if (g_is64) {
        const long long* ei = (const long long*)ei_raw;
        u = (int)ei[e];
        v = (int)ei[N_EDGES + e];
    } else {
        const int* ei = (const int*)ei_raw;
        u = ei[e];
        v = ei[N_EDGES + e];
    }
    u &= (N_NODES - 1);
    v &= (N_NODES - 1);
    atomicOr(&g_mask[u * MW + (v >> 5)], 1u << (v & 31));
    atomicOr(&g_mask[v * MW + (u >> 5)], 1u << (u & 31));
}

// ---------------------------------------------------------------------------
// 3) degree + dinv: one warp per row, uint4 loads. deg = popcount + 1
// ---------------------------------------------------------------------------
__global__ void k_degree() {
    int row  = blockIdx.x * (blockDim.x >> 5) + (threadIdx.x >> 5);
    int lane = threadIdx.x & 31;
    if (row >= N_NODES) return;
    const uint4* m = (const uint4*)&g_mask[row * MW];   // 64 uint4 per row
    int cnt = 0;
    #pragma unroll
    for (int w = 0; w < 2; w++) {
        uint4 q = m[lane + w * 32];
        cnt += __popc(q.x) + __popc(q.y) + __popc(q.z) + __popc(q.w);
    }
    #pragma unroll
    for (int o = 16; o; o >>= 1) cnt += __shfl_xor_sync(0xffffffffu, cnt, o);
    if (lane == 0) g_dinv[row] = rsqrtf((float)(cnt + 1));
}

// ---------------------------------------------------------------------------
// 3b) split fp32 -> bf16 hi + bf16 lo  (x = hi + lo + O(2^-16 x))
// ---------------------------------------------------------------------------
__global__ void k_split4(const float4* __restrict__ src,
                         __nv_bfloat162* __restrict__ hi,
                         __nv_bfloat162* __restrict__ lo, int n4) {
    int i = blockIdx.x * blockDim.x + threadIdx.x;
    if (i >= n4) return;
    float4 v = src[i];
    __nv_bfloat16 hx = __float2bfloat16_rn(v.x);
    __nv_bfloat16 hy = __float2bfloat16_rn(v.y);
    __nv_bfloat16 hz = __float2bfloat16_rn(v.z);
    __nv_bfloat16 hw = __float2bfloat16_rn(v.w);
    hi[2 * i]     = __nv_bfloat162(hx, hy);
    hi[2 * i + 1] = __nv_bfloat162(hz, hw);
    lo[2 * i]     = __nv_bfloat162(__float2bfloat16_rn(v.x - __bfloat162float(hx)),
                                   __float2bfloat16_rn(v.y - __bfloat162float(hy)));
    lo[2 * i + 1] = __nv_bfloat162(__float2bfloat16_rn(v.z - __bfloat162float(hz)),
                                   __float2bfloat16_rn(v.w - __bfloat162float(hw)));
}

// ---------------------------------------------------------------------------
// 4) Tensor-core GEMM with bf16 hi/lo split (3 mma passes, fp32 acc):
//    H'[m][n] = dinv[m] * sum_k X[m][k]*W[k][n]   (stored fp16)
// ---------------------------------------------------------------------------
#define GBM 128
#define GBN 128
#define GBK 32
#define ASTRIDE 40
#define BSTRIDE 144

__device__ __forceinline__ void ldsm_x4(uint32_t* r, const void* p) {
    uint32_t a = (uint32_t)__cvta_generic_to_shared(p);
    asm volatile("ldmatrix.sync.aligned.m8n8.x4.shared.b16 {%0,%1,%2,%3}, [%4];"
                 : "=r"(r[0]), "=r"(r[1]), "=r"(r[2]), "=r"(r[3]) : "r"(a));
}
__device__ __forceinline__ void ldsm_x4t(uint32_t* r, const void* p) {
    uint32_t a = (uint32_t)__cvta_generic_to_shared(p);
    asm volatile("ldmatrix.sync.aligned.m8n8.x4.trans.shared.b16 {%0,%1,%2,%3}, [%4];"
                 : "=r"(r[0]), "=r"(r[1]), "=r"(r[2]), "=r"(r[3]) : "r"(a));
}
__device__ __forceinline__ void mma16816(float* c, const uint32_t* a, const uint32_t* b) {
    asm volatile("mma.sync.aligned.m16n8k16.row.col.f32.bf16.bf16.f32 "
                 "{%0,%1,%2,%3}, {%4,%5,%6,%7}, {%8,%9}, {%0,%1,%2,%3};"
                 : "+f"(c[0]), "+f"(c[1]), "+f"(c[2]), "+f"(c[3])
                 : "r"(a[0]), "r"(a[1]), "r"(a[2]), "r"(a[3]), "r"(b[0]), "r"(b[1]));
}

__global__ __launch_bounds__(256) void k_gemm_mma() {
    __shared__ __nv_bfloat16 Ah[GBM * ASTRIDE], Al[GBM * ASTRIDE];
    __shared__ __nv_bfloat16 Bh[GBK * BSTRIDE], Bl[GBK * BSTRIDE];

    int tid  = threadIdx.x;
    int lane = tid & 31;
    int wid  = tid >> 5;
    int wm   = wid & 1;
    int wn   = wid >> 1;
    int rowBase = blockIdx.y * GBM;
    int colBase = blockIdx.x * GBN;

    int ar = tid >> 2, ac = (tid & 3) * 8;
    int br = tid >> 4, bc = (tid & 15) * 8;

    float acc[4][4][4];
    #pragma unroll
    for (int mi = 0; mi < 4; mi++)
        #pragma unroll
        for (int ni = 0; ni < 4; ni++)
            #pragma unroll
            for (int q = 0; q < 4; q++) acc[mi][ni][q] = 0.0f;

    uint4 pAh[2], pAl[2], pBh[2], pBl[2];
    #pragma unroll
    for (int p = 0; p < 2; p++) {
        pAh[p] = *(const uint4*)&g_xhi[(rowBase + ar + p * 64) * D + ac];
        pAl[p] = *(const uint4*)&g_xlo[(rowBase + ar + p * 64) * D + ac];
        pBh[p] = *(const uint4*)&g_whi[(br + p * 16) * D + colBase + bc];
        pBl[p] = *(const uint4*)&g_wlo[(br + p * 16) * D + colBase + bc];
    }

    for (int kt = 0; kt < D; kt += GBK) {
        __syncthreads();
        #pragma unroll
        for (int p = 0; p < 2; p++) {
            *(uint4*)&Ah[(ar + p * 64) * ASTRIDE + ac] = pAh[p];
            *(uint4*)&Al[(ar + p * 64) * ASTRIDE + ac] = pAl[p];
            *(uint4*)&Bh[(br + p * 16) * BSTRIDE + bc] = pBh[p];
            *(uint4*)&Bl[(br + p * 16) * BSTRIDE + bc] = pBl[p];
        }
        __syncthreads();

        if (kt + GBK < D) {
            int kn = kt + GBK;
            #pragma unroll
            for (int p = 0; p < 2; p++) {
                pAh[p] = *(const uint4*)&g_xhi[(rowBase + ar + p * 64) * D + kn + ac];
                pAl[p] = *(const uint4*)&g_xlo[(rowBase + ar + p * 64) * D + kn + ac];
                pBh[p] = *(const uint4*)&g_whi[(kn + br + p * 16) * D + colBase + bc];
                pBl[p] = *(const uint4*)&g_wlo[(kn + br + p * 16) * D + colBase + bc];
            }
        }

        #pragma unroll
        for (int kk = 0; kk < GBK; kk += 16) {
            uint32_t afh[4][4], afl[4][4];
            #pragma unroll
            for (int mi = 0; mi < 4; mi++) {
                int r = wm * 64 + mi * 16 + (lane & 15);
                int c = kk + ((lane >> 4) << 3);
                ldsm_x4(afh[mi], &Ah[r * ASTRIDE + c]);
                ldsm_x4(afl[mi], &Al[r * ASTRIDE + c]);
            }
            uint32_t bfh[4][2], bfl[4][2];
            #pragma unroll
            for (int np = 0; np < 2; np++) {
                int r = kk + (lane & 15);
                int c = wn * 32 + np * 16 + ((lane >> 4) << 3);
                uint32_t t4[4];
                ldsm_x4t(t4, &Bh[r * BSTRIDE + c]);
                bfh[2 * np][0] = t4[0]; bfh[2 * np][1] = t4[1];
                bfh[2 * np + 1][0] = t4[2]; bfh[2 * np + 1][1] = t4[3];
                ldsm_x4t(t4, &Bl[r * BSTRIDE + c]);
                bfl[2 * np][0] = t4[0]; bfl[2 * np][1] = t4[1];
                bfl[2 * np + 1][0] = t4[2]; bfl[2 * np + 1][1] = t4[3];
            }
            #pragma unroll
            for (int mi = 0; mi < 4; mi++)
                #pragma unroll
                for (int ni = 0; ni < 4; ni++) {
                    mma16816(acc[mi][ni], afh[mi], bfh[ni]);   // hi*hi
                    mma16816(acc[mi][ni], afh[mi], bfl[ni]);   // hi*lo
                    mma16816(acc[mi][ni], afl[mi], bfh[ni]);   // lo*hi
                }
        }
    }

    // epilogue: scale by dinv[row], write fp16 H'
    int g  = lane >> 2;
    int tg = lane & 3;
    #pragma unroll
    for (int mi = 0; mi < 4; mi++) {
        int row0 = rowBase + wm * 64 + mi * 16 + g;
        int row1 = row0 + 8;
        float s0 = g_dinv[row0], s1 = g_dinv[row1];
        #pragma unroll
        for (int ni = 0; ni < 4; ni++) {
            int col = colBase + wn * 32 + ni * 8 + tg * 2;
            __half2 v0 = __floats2half2_rn(s0 * acc[mi][ni][0], s0 * acc[mi][ni][1]);
            __half2 v1 = __floats2half2_rn(s1 * acc[mi][ni][2], s1 * acc[mi][ni][3]);
            *(__half2*)&g_h[row0 * D + col] = v0;
            *(__half2*)&g_h[row1 * D + col] = v1;
        }
    }
}

// ---------------------------------------------------------------------------
// 5) SpMM gather (fp16 payload): out[i] = dinv[i]*(sum_j H'[j] + H'[i]) + b
//    bitmask -> smem index list, stride-4 gather, fp32 accumulation.
//    Each thread owns 4 fp16 (uint2) of the 512-wide row.
// ---------------------------------------------------------------------------
#define LIST_CAP 4096

__device__ __forceinline__ void acc_h4(float4& a, uint2 u) {
    float2 lo = __half22float2(*(const __half2*)&u.x);
    float2 hi = __half22float2(*(const __half2*)&u.y);
    a.x += lo.x; a.y += lo.y; a.z += hi.x; a.w += hi.y;
}

__global__ __launch_bounds__(128) void k_spmm(const float* __restrict__ bias,
                                              float* __restrict__ out) {
    __shared__ unsigned int smask[MW];
    __shared__ unsigned short list[LIST_CAP];
    __shared__ int wsum[4];

    int row  = blockIdx.x;
    int tid  = threadIdx.x;
    int lane = tid & 31;
    int wrp  = tid >> 5;

    smask[tid]       = g_mask[row * MW + tid];
    smask[tid + 128] = g_mask[row * MW + tid + 128];
    __syncthreads();

    unsigned int w0 = smask[2 * tid], w1 = smask[2 * tid + 1];
    int c = __popc(w0) + __popc(w1);
    int p = c;
    #pragma unroll
    for (int o = 1; o < 32; o <<= 1) {
        int t = __shfl_up_sync(0xffffffffu, p, o);
        if (lane >= o) p += t;
    }
    if (lane == 31) wsum[wrp] = p;
    __syncthreads();
    int wbase = 0;
    #pragma unroll
    for (int w = 0; w < 4; w++) wbase += (w < wrp) ? wsum[w] : 0;
    int total = wsum[0] + wsum[1] + wsum[2] + wsum[3];

    const uint2* H2 = (const uint2*)g_h;   // 128 uint2 per 512-fp16 row

    float4 acc0 = make_float4(0, 0, 0, 0);
    float4 acc1 = make_float4(0, 0, 0, 0);
    float4 acc2 = make_float4(0, 0, 0, 0);
    float4 acc3 = make_float4(0, 0, 0, 0);
    acc_h4(acc0, H2[row * (D / 4) + tid]);   // identity term

    if (total <= LIST_CAP) {
        int off = wbase + p - c;  // exclusive prefix
        unsigned int bits = w0;
        int base = (2 * tid) << 5;
        while (bits) { int b = __ffs(bits) - 1; bits &= bits - 1; list[off++] = (unsigned short)(base + b); }
        bits = w1; base = (2 * tid + 1) << 5;
        while (bits) { int b = __ffs(bits) - 1; bits &= bits - 1; list[off++] = (unsigned short)(base + b); }
        __syncthreads();

        int i = 0;
        for (; i + 4 <= total; i += 4) {
            int j0 = list[i], j1 = list[i + 1], j2 = list[i + 2], j3 = list[i + 3];
            uint2 u0 = H2[j0 * (D / 4) + tid];
            uint2 u1 = H2[j1 * (D / 4) + tid];
            uint2 u2 = H2[j2 * (D / 4) + tid];
            uint2 u3 = H2[j3 * (D / 4) + tid];
            acc_h4(acc0, u0);
            acc_h4(acc1, u1);
            acc_h4(acc2, u2);
            acc_h4(acc3, u3);
        }
        for (; i < total; i++) acc_h4(acc0, H2[list[i] * (D / 4) + tid]);
    } else {
        for (int w = 0; w < MW; w++) {
            unsigned int bits = smask[w];
            while (bits) {
                int b = __ffs(bits) - 1;
                bits &= bits - 1;
                acc_h4(acc0, H2[((w << 5) + b) * (D / 4) + tid]);
            }
        }
    }

    acc0.x += acc1.x + acc2.x + acc3.x;
    acc0.y += acc1.y + acc2.y + acc3.y;
    acc0.z += acc1.z + acc2.z + acc3.z;
    acc0.w += acc1.w + acc2.w + acc3.w;

    float s   = g_dinv[row];
    float4 bb = ((const float4*)bias)[tid];
    float4 o;
    o.x = s * acc0.x + bb.x;
    o.y = s * acc0.y + bb.y;
    o.z = s * acc0.z + bb.z;
    o.w = s * acc0.w + bb.w;
    ((float4*)out)[row * (D / 4) + tid] = o;
}

// ---------------------------------------------------------------------------
// launch
// ---------------------------------------------------------------------------
extern "C" void kernel_launch(void* const* d_in, const int* in_sizes, int n_in,
                              void* d_out, int out_size) {
    const float* x    = (const float*)d_in[0];
    const void*  ei   = d_in[1];
    const float* w    = (const float*)d_in[2];
    const float* bias = (const float*)d_in[3];
    float*       out  = (float*)d_out;

    k_detect<<<1, 256>>>((const int*)ei);
    k_zero_mask<<<(N_NODES * MW / 4 + 255) / 256, 256>>>();
    k_scatter<<<(N_EDGES + 255) / 256, 256>>>(ei);
    k_degree<<<N_NODES / 8, 256>>>();

    __nv_bfloat162 *xhi, *xlo, *whi, *wlo;
    cudaGetSymbolAddress((void**)&xhi, g_xhi);
    cudaGetSymbolAddress((void**)&xlo, g_xlo);
    cudaGetSymbolAddress((void**)&whi, g_whi);
    cudaGetSymbolAddress((void**)&wlo, g_wlo);

    int nx4 = N_NODES * D / 4;
    int nw4 = D * D / 4;
    k_split4<<<(nx4 + 255) / 256, 256>>>((const float4*)x, xhi, xlo, nx4);
    k_split4<<<(nw4 + 255) / 256, 256>>>((const float4*)w, whi, wlo, nw4);

    dim3 gemmGrid(D / GBN, N_NODES / GBM);
    k_gemm_mma<<<gemmGrid, 256>>>();

    k_spmm<<<N_NODES, 128>>>(bias, out);
}

// round 5
// speedup vs baseline: 1.5413x; 1.5413x over previous
#include <cuda_runtime.h>
#include <cuda_bf16.h>
#include <cuda_fp16.h>
#include <cstdint>

#define N_NODES 8192
#define N_EDGES 262144
#define D 512
#define MW 256   // 8192 bits / 32 = 256 mask words per row

// Scratch (device globals; no allocations allowed)
__device__ unsigned int g_mask[N_NODES * MW];                    // 8 MB adjacency bitmask
__device__ float        g_dinv[N_NODES];                         // D^{-1/2}
__device__ __align__(16) __half g_h[N_NODES * D];                // H' = dinv*(X@W), fp16
__device__ int          g_is64;                                  // edge_index dtype flag
__device__ __align__(16) __nv_bfloat16 g_xhi[N_NODES * D];       // bf16 split of X
__device__ __align__(16) __nv_bfloat16 g_xlo[N_NODES * D];
__device__ __align__(16) __nv_bfloat16 g_whi[D * D];             // bf16 split of W
__device__ __align__(16) __nv_bfloat16 g_wlo[D * D];

// ---------------------------------------------------------------------------
// 0) detect edge_index dtype (int64 vs int32)
// ---------------------------------------------------------------------------
__global__ void k_detect(const int* __restrict__ ei32) {
    int t = threadIdx.x;
    int nz = 0;
    #pragma unroll
    for (int i = t; i < 4096; i += 256) nz |= ei32[2 * i + 1];
    int any = __syncthreads_or(nz != 0);
    if (t == 0) g_is64 = any ? 0 : 1;
}

// ---------------------------------------------------------------------------
// 1) zero bitmask (vectorized)
// ---------------------------------------------------------------------------
__global__ void k_zero_mask() {
    int i = blockIdx.x * blockDim.x + threadIdx.x;
    if (i < N_NODES * MW / 4) ((uint4*)g_mask)[i] = make_uint4(0, 0, 0, 0);
}

// ---------------------------------------------------------------------------
// 2) symmetric edge scatter into bitmask (dedup for free)
// ---------------------------------------------------------------------------
__global__ void k_scatter(const void* __restrict__ ei_raw) {
    int e = blockIdx.x * blockDim.x + threadIdx.x;
    if (e >= N_EDGES) return;
    int u, v;
    if (g_is64) {
        const long long* ei = (const long long*)ei_raw;
        u = (int)ei[e];
        v = (int)ei[N_EDGES + e];
    } else {
        const int* ei = (const int*)ei_raw;
        u = ei[e];
        v = ei[N_EDGES + e];
    }
    u &= (N_NODES - 1);
    v &= (N_NODES - 1);
    atomicOr(&g_mask[u * MW + (v >> 5)], 1u << (v & 31));
    atomicOr(&g_mask[v * MW + (u >> 5)], 1u << (u & 31));
}

// ---------------------------------------------------------------------------
// 3) degree + dinv: one warp per row. deg = popcount + 1 (identity)
// ---------------------------------------------------------------------------
__global__ void k_degree() {
    int row  = blockIdx.x * (blockDim.x >> 5) + (threadIdx.x >> 5);
    int lane = threadIdx.x & 31;
    if (row >= N_NODES) return;
    const uint4* m = (const uint4*)&g_mask[row * MW];
    int cnt = 0;
    #pragma unroll
    for (int w = 0; w < 2; w++) {
        uint4 q = m[lane + w * 32];
        cnt += __popc(q.x) + __popc(q.y) + __popc(q.z) + __popc(q.w);
    }
    #pragma unroll
    for (int o = 16; o; o >>= 1) cnt += __shfl_xor_sync(0xffffffffu, cnt, o);
    if (lane == 0) g_dinv[row] = rsqrtf((float)(cnt + 1));
}

// ---------------------------------------------------------------------------
// 3b) split fp32 -> bf16 hi + bf16 lo
// ---------------------------------------------------------------------------
__global__ void k_split4(const float4* __restrict__ src,
                         __nv_bfloat162* __restrict__ hi,
                         __nv_bfloat162* __restrict__ lo, int n4) {
    int i = blockIdx.x * blockDim.x + threadIdx.x;
    if (i >= n4) return;
    float4 v = src[i];
    __nv_bfloat16 hx = __float2bfloat16_rn(v.x);
    __nv_bfloat16 hy = __float2bfloat16_rn(v.y);
    __nv_bfloat16 hz = __float2bfloat16_rn(v.z);
    __nv_bfloat16 hw = __float2bfloat16_rn(v.w);
    hi[2 * i]     = __nv_bfloat162(hx, hy);
    hi[2 * i + 1] = __nv_bfloat162(hz, hw);
    lo[2 * i]     = __nv_bfloat162(__float2bfloat16_rn(v.x - __bfloat162float(hx)),
                                   __float2bfloat16_rn(v.y - __bfloat162float(hy)));
    lo[2 * i + 1] = __nv_bfloat162(__float2bfloat16_rn(v.z - __bfloat162float(hz)),
                                   __float2bfloat16_rn(v.w - __bfloat162float(hw)));
}

// ---------------------------------------------------------------------------
// 4) Tensor-core GEMM with bf16 hi/lo split (3 mma passes, fp32 acc):
//    H'[m][n] = dinv[m] * sum_k X[m][k]*W[k][n]   (stored fp16)
// ---------------------------------------------------------------------------
#define GBM 128
#define GBN 128
#define GBK 32
#define ASTRIDE 40
#define BSTRIDE 144

__device__ __forceinline__ void ldsm_x4(uint32_t* r, const void* p) {
    uint32_t a = (uint32_t)__cvta_generic_to_shared(p);
    asm volatile("ldmatrix.sync.aligned.m8n8.x4.shared.b16 {%0,%1,%2,%3}, [%4];"
                 : "=r"(r[0]), "=r"(r[1]), "=r"(r[2]), "=r"(r[3]) : "r"(a));
}
__device__ __forceinline__ void ldsm_x4t(uint32_t* r, const void* p) {
    uint32_t a = (uint32_t)__cvta_generic_to_shared(p);
    asm volatile("ldmatrix.sync.aligned.m8n8.x4.trans.shared.b16 {%0,%1,%2,%3}, [%4];"
                 : "=r"(r[0]), "=r"(r[1]), "=r"(r[2]), "=r"(r[3]) : "r"(a));
}
__device__ __forceinline__ void mma16816(float* c, const uint32_t* a, const uint32_t* b) {
    asm volatile("mma.sync.aligned.m16n8k16.row.col.f32.bf16.bf16.f32 "
                 "{%0,%1,%2,%3}, {%4,%5,%6,%7}, {%8,%9}, {%0,%1,%2,%3};"
                 : "+f"(c[0]), "+f"(c[1]), "+f"(c[2]), "+f"(c[3])
                 : "r"(a[0]), "r"(a[1]), "r"(a[2]), "r"(a[3]), "r"(b[0]), "r"(b[1]));
}

__global__ __launch_bounds__(256) void k_gemm_mma() {
    __shared__ __nv_bfloat16 Ah[GBM * ASTRIDE], Al[GBM * ASTRIDE];
    __shared__ __nv_bfloat16 Bh[GBK * BSTRIDE], Bl[GBK * BSTRIDE];

    int tid  = threadIdx.x;
    int lane = tid & 31;
    int wid  = tid >> 5;
    int wm   = wid & 1;
    int wn   = wid >> 1;
    int rowBase = blockIdx.y * GBM;
    int colBase = blockIdx.x * GBN;

    int ar = tid >> 2, ac = (tid & 3) * 8;
    int br = tid >> 4, bc = (tid & 15) * 8;

    float acc[4][4][4];
    #pragma unroll
    for (int mi = 0; mi < 4; mi++)
        #pragma unroll
        for (int ni = 0; ni < 4; ni++)
            #pragma unroll
            for (int q = 0; q < 4; q++) acc[mi][ni][q] = 0.0f;

    uint4 pAh[2], pAl[2], pBh[2], pBl[2];
    #pragma unroll
    for (int p = 0; p < 2; p++) {
        pAh[p] = *(const uint4*)&g_xhi[(rowBase + ar + p * 64) * D + ac];
        pAl[p] = *(const uint4*)&g_xlo[(rowBase + ar + p * 64) * D + ac];
        pBh[p] = *(const uint4*)&g_whi[(br + p * 16) * D + colBase + bc];
        pBl[p] = *(const uint4*)&g_wlo[(br + p * 16) * D + colBase + bc];
    }

    for (int kt = 0; kt < D; kt += GBK) {
        __syncthreads();
        #pragma unroll
        for (int p = 0; p < 2; p++) {
            *(uint4*)&Ah[(ar + p * 64) * ASTRIDE + ac] = pAh[p];
            *(uint4*)&Al[(ar + p * 64) * ASTRIDE + ac] = pAl[p];
            *(uint4*)&Bh[(br + p * 16) * BSTRIDE + bc] = pBh[p];
            *(uint4*)&Bl[(br + p * 16) * BSTRIDE + bc] = pBl[p];
        }
        __syncthreads();

        if (kt + GBK < D) {
            int kn = kt + GBK;
            #pragma unroll
            for (int p = 0; p < 2; p++) {
                pAh[p] = *(const uint4*)&g_xhi[(rowBase + ar + p * 64) * D + kn + ac];
                pAl[p] = *(const uint4*)&g_xlo[(rowBase + ar + p * 64) * D + kn + ac];
                pBh[p] = *(const uint4*)&g_whi[(kn + br + p * 16) * D + colBase + bc];
                pBl[p] = *(const uint4*)&g_wlo[(kn + br + p * 16) * D + colBase + bc];
            }
        }

        #pragma unroll
        for (int kk = 0; kk < GBK; kk += 16) {
            uint32_t afh[4][4], afl[4][4];
            #pragma unroll
            for (int mi = 0; mi < 4; mi++) {
                int r = wm * 64 + mi * 16 + (lane & 15);
                int c = kk + ((lane >> 4) << 3);
                ldsm_x4(afh[mi], &Ah[r * ASTRIDE + c]);
                ldsm_x4(afl[mi], &Al[r * ASTRIDE + c]);
            }
            uint32_t bfh[4][2], bfl[4][2];
            #pragma unroll
            for (int np = 0; np < 2; np++) {
                int r = kk + (lane & 15);
                int c = wn * 32 + np * 16 + ((lane >> 4) << 3);
                uint32_t t4[4];
                ldsm_x4t(t4, &Bh[r * BSTRIDE + c]);
                bfh[2 * np][0] = t4[0]; bfh[2 * np][1] = t4[1];
                bfh[2 * np + 1][0] = t4[2]; bfh[2 * np + 1][1] = t4[3];
                ldsm_x4t(t4, &Bl[r * BSTRIDE + c]);
                bfl[2 * np][0] = t4[0]; bfl[2 * np][1] = t4[1];
                bfl[2 * np + 1][0] = t4[2]; bfl[2 * np + 1][1] = t4[3];
            }
            #pragma unroll
            for (int mi = 0; mi < 4; mi++)
                #pragma unroll
                for (int ni = 0; ni < 4; ni++) {
                    mma16816(acc[mi][ni], afh[mi], bfh[ni]);   // hi*hi
                    mma16816(acc[mi][ni], afh[mi], bfl[ni]);   // hi*lo
                    mma16816(acc[mi][ni], afl[mi], bfh[ni]);   // lo*hi
                }
        }
    }

    // epilogue: scale by dinv[row], write fp16 H'
    int g  = lane >> 2;
    int tg = lane & 3;
    #pragma unroll
    for (int mi = 0; mi < 4; mi++) {
        int row0 = rowBase + wm * 64 + mi * 16 + g;
        int row1 = row0 + 8;
        float s0 = g_dinv[row0], s1 = g_dinv[row1];
        #pragma unroll
        for (int ni = 0; ni < 4; ni++) {
            int col = colBase + wn * 32 + ni * 8 + tg * 2;
            __half2 v0 = __floats2half2_rn(s0 * acc[mi][ni][0], s0 * acc[mi][ni][1]);
            __half2 v1 = __floats2half2_rn(s1 * acc[mi][ni][2], s1 * acc[mi][ni][3]);
            *(__half2*)&g_h[row0 * D + col] = v0;
            *(__half2*)&g_h[row1 * D + col] = v1;
        }
    }
}

// ---------------------------------------------------------------------------
// 5) SpMM gather (fp16 payload, 16B loads):
//    out[i] = dinv[i]*(sum_j H'[j] + H'[i]) + bias
//    128 threads = two 64-thread halves. Each half covers the FULL row width
//    (8 fp16 cols per thread, one uint4/LDG.128 per neighbor) and processes a
//    contiguous half of the neighbor list; halves combine via smem.
//    64 LDG.128 per neighbor row (vs 128 in fp32): halves bytes AND wavefronts.
// ---------------------------------------------------------------------------
#define LIST_CAP 4096

__device__ __forceinline__ void acc_h8(float4& a, float4& b, uint4 u) {
    float2 f;
    f = __half22float2(*(const __half2*)&u.x); a.x += f.x; a.y += f.y;
    f = __half22float2(*(const __half2*)&u.y); a.z += f.x; a.w += f.y;
    f = __half22float2(*(const __half2*)&u.z); b.x += f.x; b.y += f.y;
    f = __half22float2(*(const __half2*)&u.w); b.z += f.x; b.w += f.y;
}

__global__ __launch_bounds__(128) void k_spmm(const float* __restrict__ bias,
                                              float* __restrict__ out) {
    __shared__ unsigned int smask[MW];
    __shared__ unsigned short list[LIST_CAP];
    __shared__ int wsum[4];
    __shared__ __align__(16) float part[64 * 8];   // 2 KB combine buffer

    int row  = blockIdx.x;
    int tid  = threadIdx.x;
    int lane = tid & 31;
    int wrp  = tid >> 5;

    smask[tid]       = g_mask[row * MW + tid];
    smask[tid + 128] = g_mask[row * MW + tid + 128];
    __syncthreads();

    // counts + deterministic block scan -> compact neighbor list
    unsigned int w0 = smask[2 * tid], w1 = smask[2 * tid + 1];
    int c = __popc(w0) + __popc(w1);
    int p = c;
    #pragma unroll
    for (int o = 1; o < 32; o <<= 1) {
        int t = __shfl_up_sync(0xffffffffu, p, o);
        if (lane >= o) p += t;
    }
    if (lane == 31) wsum[wrp] = p;
    __syncthreads();
    int wbase = 0;
    #pragma unroll
    for (int w = 0; w < 4; w++) wbase += (w < wrp) ? wsum[w] : 0;
    int total = wsum[0] + wsum[1] + wsum[2] + wsum[3];

    bool uselist = (total <= LIST_CAP);
    if (uselist) {
        int off = wbase + p - c;
        unsigned int bits = w0;
        int base = (2 * tid) << 5;
        while (bits) { int b = __ffs(bits) - 1; bits &= bits - 1; list[off++] = (unsigned short)(base + b); }
        bits = w1; base = (2 * tid + 1) << 5;
        while (bits) { int b = __ffs(bits) - 1; bits &= bits - 1; list[off++] = (unsigned short)(base + b); }
    }
    __syncthreads();

    int tid2 = tid & 63;       // column-slice owner: cols [tid2*8, tid2*8+8)
    int half = tid >> 6;       // 0 or 1: which half of the neighbor list

    const uint4* H4 = (const uint4*)g_h;   // 64 uint4 per 512-fp16 row

    float4 a0 = make_float4(0,0,0,0), b0 = make_float4(0,0,0,0);
    float4 a1 = make_float4(0,0,0,0), b1 = make_float4(0,0,0,0);
    float4 a2 = make_float4(0,0,0,0), b2 = make_float4(0,0,0,0);
    float4 a3 = make_float4(0,0,0,0), b3 = make_float4(0,0,0,0);

    if (half == 0) acc_h8(a0, b0, H4[row * 64 + tid2]);   // identity term

    if (uselist) {
        int mid = total >> 1;
        int lo = half ? mid : 0;
        int hi = half ? total : mid;
        int i = lo;
        for (; i + 4 <= hi; i += 4) {
            uint4 u0 = H4[list[i]     * 64 + tid2];
            uint4 u1 = H4[list[i + 1] * 64 + tid2];
            uint4 u2 = H4[list[i + 2] * 64 + tid2];
            uint4 u3 = H4[list[i + 3] * 64 + tid2];
            acc_h8(a0, b0, u0);
            acc_h8(a1, b1, u1);
            acc_h8(a2, b2, u2);
            acc_h8(a3, b3, u3);
        }
        for (; i < hi; i++) acc_h8(a0, b0, H4[list[i] * 64 + tid2]);
    } else {
        // fallback: direct bit-walk, words split between halves
        for (int w = half * 128; w < half * 128 + 128; w++) {
            unsigned int bits = smask[w];
            while (bits) {
                int b = __ffs(bits) - 1;
                bits &= bits - 1;
                acc_h8(a0, b0, H4[((w << 5) + b) * 64 + tid2]);
            }
        }
    }

    a0.x += a1.x + a2.x + a3.x;  a0.y += a1.y + a2.y + a3.y;
    a0.z += a1.z + a2.z + a3.z;  a0.w += a1.w + a2.w + a3.w;
    b0.x += b1.x + b2.x + b3.x;  b0.y += b1.y + b2.y + b3.y;
    b0.z += b1.z + b2.z + b3.z;  b0.w += b1.w + b2.w + b3.w;

    // combine halves via smem
    if (half == 1) {
        ((float4*)part)[tid2 * 2]     = a0;
        ((float4*)part)[tid2 * 2 + 1] = b0;
    }
    __syncthreads();
    if (half == 0) {
        float4 pa = ((float4*)part)[tid2 * 2];
        float4 pb = ((float4*)part)[tid2 * 2 + 1];
        a0.x += pa.x; a0.y += pa.y; a0.z += pa.z; a0.w += pa.w;
        b0.x += pb.x; b0.y += pb.y; b0.z += pb.z; b0.w += pb.w;

        float s = g_dinv[row];
        float4 bia = ((const float4*)bias)[tid2 * 2];
        float4 bib = ((const float4*)bias)[tid2 * 2 + 1];
        float4 o0, o1;
        o0.x = s * a0.x + bia.x; o0.y = s * a0.y + bia.y;
        o0.z = s * a0.z + bia.z; o0.w = s * a0.w + bia.w;
        o1.x = s * b0.x + bib.x; o1.y = s * b0.y + bib.y;
        o1.z = s * b0.z + bib.z; o1.w = s * b0.w + bib.w;
        ((float4*)out)[row * (D / 4) + tid2 * 2]     = o0;
        ((float4*)out)[row * (D / 4) + tid2 * 2 + 1] = o1;
    }
}

// ---------------------------------------------------------------------------
// launch
// ---------------------------------------------------------------------------
extern "C" void kernel_launch(void* const* d_in, const int* in_sizes, int n_in,
                              void* d_out, int out_size) {
    const float* x    = (const float*)d_in[0];
    const void*  ei   = d_in[1];
    const float* w    = (const float*)d_in[2];
    const float* bias = (const float*)d_in[3];
    float*       out  = (float*)d_out;

    k_detect<<<1, 256>>>((const int*)ei);
    k_zero_mask<<<(N_NODES * MW / 4 + 255) / 256, 256>>>();
    k_scatter<<<(N_EDGES + 255) / 256, 256>>>(ei);
    k_degree<<<N_NODES / 8, 256>>>();

    __nv_bfloat162 *xhi, *xlo, *whi, *wlo;
    cudaGetSymbolAddress((void**)&xhi, g_xhi);
    cudaGetSymbolAddress((void**)&xlo, g_xlo);
    cudaGetSymbolAddress((void**)&whi, g_whi);
    cudaGetSymbolAddress((void**)&wlo, g_wlo);

    int nx4 = N_NODES * D / 4;
    int nw4 = D * D / 4;
    k_split4<<<(nx4 + 255) / 256, 256>>>((const float4*)x, xhi, xlo, nx4);
    k_split4<<<(nw4 + 255) / 256, 256>>>((const float4*)w, whi, wlo, nw4);

    dim3 gemmGrid(D / GBN, N_NODES / GBM);
    k_gemm_mma<<<gemmGrid, 256>>>();

    k_spmm<<<N_NODES, 128>>>(bias, out);
}

// round 6
// speedup vs baseline: 1.9954x; 1.2946x over previous
#include <cuda_runtime.h>
#include <cuda_fp16.h>
#include <cstdint>

#define N_NODES 8192
#define N_EDGES 262144
#define D 512
#define MW 256   // 8192 bits / 32 = 256 mask words per row

// Scratch (device globals; no allocations allowed)
__device__ unsigned int g_mask[N_NODES * MW];           // 8 MB adjacency bitmask
__device__ float        g_dinv[N_NODES];                // D^{-1/2}
__device__ __align__(16) __half g_h[N_NODES * D];       // H' = dinv*(X@W), fp16
__device__ int          g_is64;                         // edge_index dtype flag
__device__ __align__(16) __half g_xh[N_NODES * D];      // fp16 X
__device__ __align__(16) __half g_wh[D * D];            // fp16 W

// ---------------------------------------------------------------------------
// 0) detect edge_index dtype (int64 vs int32)
// ---------------------------------------------------------------------------
__global__ void k_detect(const int* __restrict__ ei32) {
    int t = threadIdx.x;
    int nz = 0;
    #pragma unroll
    for (int i = t; i < 4096; i += 256) nz |= ei32[2 * i + 1];
    int any = __syncthreads_or(nz != 0);
    if (t == 0) g_is64 = any ? 0 : 1;
}

// ---------------------------------------------------------------------------
// 1) zero bitmask (vectorized)
// ---------------------------------------------------------------------------
__global__ void k_zero_mask() {
    int i = blockIdx.x * blockDim.x + threadIdx.x;
    if (i < N_NODES * MW / 4) ((uint4*)g_mask)[i] = make_uint4(0, 0, 0, 0);
}

// ---------------------------------------------------------------------------
// 2) symmetric edge scatter into bitmask (dedup for free)
// ---------------------------------------------------------------------------
__global__ void k_scatter(const void* __restrict__ ei_raw) {
    int e = blockIdx.x * blockDim.x + threadIdx.x;
    if (e >= N_EDGES) return;
    int u, v;
    if (g_is64) {
        const long long* ei = (const long long*)ei_raw;
        u = (int)ei[e];
        v = (int)ei[N_EDGES + e];
    } else {
        const int* ei = (const int*)ei_raw;
        u = ei[e];
        v = ei[N_EDGES + e];
    }
    u &= (N_NODES - 1);
    v &= (N_NODES - 1);
    atomicOr(&g_mask[u * MW + (v >> 5)], 1u << (v & 31));
    atomicOr(&g_mask[v * MW + (u >> 5)], 1u << (u & 31));
}

// ---------------------------------------------------------------------------
// 3) degree + dinv: one warp per row. deg = popcount + 1 (identity)
// ---------------------------------------------------------------------------
__global__ void k_degree() {
    int row  = blockIdx.x * (blockDim.x >> 5) + (threadIdx.x >> 5);
    int lane = threadIdx.x & 31;
    if (row >= N_NODES) return;
    const uint4* m = (const uint4*)&g_mask[row * MW];
    int cnt = 0;
    #pragma unroll
    for (int w = 0; w < 2; w++) {
        uint4 q = m[lane + w * 32];
        cnt += __popc(q.x) + __popc(q.y) + __popc(q.z) + __popc(q.w);
    }
    #pragma unroll
    for (int o = 16; o; o >>= 1) cnt += __shfl_xor_sync(0xffffffffu, cnt, o);
    if (lane == 0) g_dinv[row] = rsqrtf((float)(cnt + 1));
}

// ---------------------------------------------------------------------------
// 3b) convert fp32 -> fp16 (8 floats / thread, one uint4 store)
// ---------------------------------------------------------------------------
__global__ void k_cvt(const float4* __restrict__ src, uint4* __restrict__ dst, int n8) {
    int i = blockIdx.x * blockDim.x + threadIdx.x;
    if (i >= n8) return;
    float4 a = src[2 * i];
    float4 b = src[2 * i + 1];
    uint4 o;
    __half2 h;
    h = __floats2half2_rn(a.x, a.y); o.x = *(uint32_t*)&h;
    h = __floats2half2_rn(a.z, a.w); o.y = *(uint32_t*)&h;
    h = __floats2half2_rn(b.x, b.y); o.z = *(uint32_t*)&h;
    h = __floats2half2_rn(b.z, b.w); o.w = *(uint32_t*)&h;
    dst[i] = o;
}

// ---------------------------------------------------------------------------
// 4) Tensor-core GEMM, single-pass fp16 (fp32 accumulate):
//    H'[m][n] = dinv[m] * sum_k X[m][k]*W[k][n]   (stored fp16)
//    128x128 block tile, BK=32, 8 warps (2x4), 64x32 warp tile, m16n8k16 mma
// ---------------------------------------------------------------------------
#define GBM 128
#define GBN 128
#define GBK 32
#define ASTRIDE 40
#define BSTRIDE 144

__device__ __forceinline__ void ldsm_x4(uint32_t* r, const void* p) {
    uint32_t a = (uint32_t)__cvta_generic_to_shared(p);
    asm volatile("ldmatrix.sync.aligned.m8n8.x4.shared.b16 {%0,%1,%2,%3}, [%4];"
                 : "=r"(r[0]), "=r"(r[1]), "=r"(r[2]), "=r"(r[3]) : "r"(a));
}
__device__ __forceinline__ void ldsm_x4t(uint32_t* r, const void* p) {
    uint32_t a = (uint32_t)__cvta_generic_to_shared(p);
    asm volatile("ldmatrix.sync.aligned.m8n8.x4.trans.shared.b16 {%0,%1,%2,%3}, [%4];"
                 : "=r"(r[0]), "=r"(r[1]), "=r"(r[2]), "=r"(r[3]) : "r"(a));
}
__device__ __forceinline__ void mma16816(float* c, const uint32_t* a, const uint32_t* b) {
    asm volatile("mma.sync.aligned.m16n8k16.row.col.f32.f16.f16.f32 "
                 "{%0,%1,%2,%3}, {%4,%5,%6,%7}, {%8,%9}, {%0,%1,%2,%3};"
                 : "+f"(c[0]), "+f"(c[1]), "+f"(c[2]), "+f"(c[3])
                 : "r"(a[0]), "r"(a[1]), "r"(a[2]), "r"(a[3]), "r"(b[0]), "r"(b[1]));
}

__global__ __launch_bounds__(256) void k_gemm_mma() {
    __shared__ __half Ah[GBM * ASTRIDE];
    __shared__ __half Bh[GBK * BSTRIDE];

    int tid  = threadIdx.x;
    int lane = tid & 31;
    int wid  = tid >> 5;
    int wm   = wid & 1;
    int wn   = wid >> 1;
    int rowBase = blockIdx.y * GBM;
    int colBase = blockIdx.x * GBN;

    int ar = tid >> 2, ac = (tid & 3) * 8;
    int br = tid >> 4, bc = (tid & 15) * 8;

    float acc[4][4][4];
    #pragma unroll
    for (int mi = 0; mi < 4; mi++)
        #pragma unroll
        for (int ni = 0; ni < 4; ni++)
            #pragma unroll
            for (int q = 0; q < 4; q++) acc[mi][ni][q] = 0.0f;

    uint4 pA[2], pB[2];
    #pragma unroll
    for (int p = 0; p < 2; p++) {
        pA[p] = *(const uint4*)&g_xh[(rowBase + ar + p * 64) * D + ac];
        pB[p] = *(const uint4*)&g_wh[(br + p * 16) * D + colBase + bc];
    }

    for (int kt = 0; kt < D; kt += GBK) {
        __syncthreads();
        #pragma unroll
        for (int p = 0; p < 2; p++) {
            *(uint4*)&Ah[(ar + p * 64) * ASTRIDE + ac] = pA[p];
            *(uint4*)&Bh[(br + p * 16) * BSTRIDE + bc] = pB[p];
        }
        __syncthreads();

        if (kt + GBK < D) {
            int kn = kt + GBK;
            #pragma unroll
            for (int p = 0; p < 2; p++) {
                pA[p] = *(const uint4*)&g_xh[(rowBase + ar + p * 64) * D + kn + ac];
                pB[p] = *(const uint4*)&g_wh[(kn + br + p * 16) * D + colBase + bc];
            }
        }

        #pragma unroll
        for (int kk = 0; kk < GBK; kk += 16) {
            uint32_t af[4][4];
            #pragma unroll
            for (int mi = 0; mi < 4; mi++) {
                int r = wm * 64 + mi * 16 + (lane & 15);
                int c = kk + ((lane >> 4) << 3);
                ldsm_x4(af[mi], &Ah[r * ASTRIDE + c]);
            }
            uint32_t bf[4][2];
            #pragma unroll
            for (int np = 0; np < 2; np++) {
                int r = kk + (lane & 15);
                int c = wn * 32 + np * 16 + ((lane >> 4) << 3);
                uint32_t t4[4];
                ldsm_x4t(t4, &Bh[r * BSTRIDE + c]);
                bf[2 * np][0] = t4[0]; bf[2 * np][1] = t4[1];
                bf[2 * np + 1][0] = t4[2]; bf[2 * np + 1][1] = t4[3];
            }
            #pragma unroll
            for (int mi = 0; mi < 4; mi++)
                #pragma unroll
                for (int ni = 0; ni < 4; ni++)
                    mma16816(acc[mi][ni], af[mi], bf[ni]);
        }
    }

    // epilogue: scale by dinv[row], write fp16 H'
    int g  = lane >> 2;
    int tg = lane & 3;
    #pragma unroll
    for (int mi = 0; mi < 4; mi++) {
        int row0 = rowBase + wm * 64 + mi * 16 + g;
        int row1 = row0 + 8;
        float s0 = g_dinv[row0], s1 = g_dinv[row1];
        #pragma unroll
        for (int ni = 0; ni < 4; ni++) {
            int col = colBase + wn * 32 + ni * 8 + tg * 2;
            __half2 v0 = __floats2half2_rn(s0 * acc[mi][ni][0], s0 * acc[mi][ni][1]);
            __half2 v1 = __floats2half2_rn(s1 * acc[mi][ni][2], s1 * acc[mi][ni][3]);
            *(__half2*)&g_h[row0 * D + col] = v0;
            *(__half2*)&g_h[row1 * D + col] = v1;
        }
    }
}

// ---------------------------------------------------------------------------
// 5) SpMM gather (fp16 payload, 16B loads):
//    out[i] = dinv[i]*(sum_j H'[j] + H'[i]) + bias
//    128 threads = two 64-thread halves; each half covers the full row width
//    (8 fp16/thread, one LDG.128 per neighbor) over half the neighbor list.
// ---------------------------------------------------------------------------
#define LIST_CAP 4096

__device__ __forceinline__ void acc_h8(float4& a, float4& b, uint4 u) {
    float2 f;
    f = __half22float2(*(const __half2*)&u.x); a.x += f.x; a.y += f.y;
    f = __half22float2(*(const __half2*)&u.y); a.z += f.x; a.w += f.y;
    f = __half22float2(*(const __half2*)&u.z); b.x += f.x; b.y += f.y;
    f = __half22float2(*(const __half2*)&u.w); b.z += f.x; b.w += f.y;
}

__global__ __launch_bounds__(128) void k_spmm(const float* __restrict__ bias,
                                              float* __restrict__ out) {
    __shared__ unsigned int smask[MW];
    __shared__ unsigned short list[LIST_CAP];
    __shared__ int wsum[4];
    __shared__ __align__(16) float part[64 * 8];   // 2 KB combine buffer

    int row  = blockIdx.x;
    int tid  = threadIdx.x;
    int lane = tid & 31;
    int wrp  = tid >> 5;

    smask[tid]       = g_mask[row * MW + tid];
    smask[tid + 128] = g_mask[row * MW + tid + 128];
    __syncthreads();

    unsigned int w0 = smask[2 * tid], w1 = smask[2 * tid + 1];
    int c = __popc(w0) + __popc(w1);
    int p = c;
    #pragma unroll
    for (int o = 1; o < 32; o <<= 1) {
        int t = __shfl_up_sync(0xffffffffu, p, o);
        if (lane >= o) p += t;
    }
    if (lane == 31) wsum[wrp] = p;
    __syncthreads();
    int wbase = 0;
    #pragma unroll
    for (int w = 0; w < 4; w++) wbase += (w < wrp) ? wsum[w] : 0;
    int total = wsum[0] + wsum[1] + wsum[2] + wsum[3];

    bool uselist = (total <= LIST_CAP);
    if (uselist) {
        int off = wbase + p - c;
        unsigned int bits = w0;
        int base = (2 * tid) << 5;
        while (bits) { int b = __ffs(bits) - 1; bits &= bits - 1; list[off++] = (unsigned short)(base + b); }
        bits = w1; base = (2 * tid + 1) << 5;
        while (bits) { int b = __ffs(bits) - 1; bits &= bits - 1; list[off++] = (unsigned short)(base + b); }
    }
    __syncthreads();

    int tid2 = tid & 63;
    int half = tid >> 6;

    const uint4* H4 = (const uint4*)g_h;

    float4 a0 = make_float4(0,0,0,0), b0 = make_float4(0,0,0,0);
    float4 a1 = make_float4(0,0,0,0), b1 = make_float4(0,0,0,0);
    float4 a2 = make_float4(0,0,0,0), b2 = make_float4(0,0,0,0);
    float4 a3 = make_float4(0,0,0,0), b3 = make_float4(0,0,0,0);

    if (half == 0) acc_h8(a0, b0, H4[row * 64 + tid2]);   // identity term

    if (uselist) {
        int mid = total >> 1;
        int lo = half ? mid : 0;
        int hi = half ? total : mid;
        int i = lo;
        for (; i + 4 <= hi; i += 4) {
            uint4 u0 = H4[list[i]     * 64 + tid2];
            uint4 u1 = H4[list[i + 1] * 64 + tid2];
            uint4 u2 = H4[list[i + 2] * 64 + tid2];
            uint4 u3 = H4[list[i + 3] * 64 + tid2];
            acc_h8(a0, b0, u0);
            acc_h8(a1, b1, u1);
            acc_h8(a2, b2, u2);
            acc_h8(a3, b3, u3);
        }
        for (; i < hi; i++) acc_h8(a0, b0, H4[list[i] * 64 + tid2]);
    } else {
        for (int w = half * 128; w < half * 128 + 128; w++) {
            unsigned int bits = smask[w];
            while (bits) {
                int b = __ffs(bits) - 1;
                bits &= bits - 1;
                acc_h8(a0, b0, H4[((w << 5) + b) * 64 + tid2]);
            }
        }
    }

    a0.x += a1.x + a2.x + a3.x;  a0.y += a1.y + a2.y + a3.y;
    a0.z += a1.z + a2.z + a3.z;  a0.w += a1.w + a2.w + a3.w;
    b0.x += b1.x + b2.x + b3.x;  b0.y += b1.y + b2.y + b3.y;
    b0.z += b1.z + b2.z + b3.z;  b0.w += b1.w + b2.w + b3.w;

    if (half == 1) {
        ((float4*)part)[tid2 * 2]     = a0;
        ((float4*)part)[tid2 * 2 + 1] = b0;
    }
    __syncthreads();
    if (half == 0) {
        float4 pa = ((float4*)part)[tid2 * 2];
        float4 pb = ((float4*)part)[tid2 * 2 + 1];
        a0.x += pa.x; a0.y += pa.y; a0.z += pa.z; a0.w += pa.w;
        b0.x += pb.x; b0.y += pb.y; b0.z += pb.z; b0.w += pb.w;

        float s = g_dinv[row];
        float4 bia = ((const float4*)bias)[tid2 * 2];
        float4 bib = ((const float4*)bias)[tid2 * 2 + 1];
        float4 o0, o1;
        o0.x = s * a0.x + bia.x; o0.y = s * a0.y + bia.y;
        o0.z = s * a0.z + bia.z; o0.w = s * a0.w + bia.w;
        o1.x = s * b0.x + bib.x; o1.y = s * b0.y + bib.y;
        o1.z = s * b0.z + bib.z; o1.w = s * b0.w + bib.w;
        ((float4*)out)[row * (D / 4) + tid2 * 2]     = o0;
        ((float4*)out)[row * (D / 4) + tid2 * 2 + 1] = o1;
    }
}

// ---------------------------------------------------------------------------
// launch
// ---------------------------------------------------------------------------
extern "C" void kernel_launch(void* const* d_in, const int* in_sizes, int n_in,
                              void* d_out, int out_size) {
    const float* x    = (const float*)d_in[0];
    const void*  ei   = d_in[1];
    const float* w    = (const float*)d_in[2];
    const float* bias = (const float*)d_in[3];
    float*       out  = (float*)d_out;

    k_detect<<<1, 256>>>((const int*)ei);
    k_zero_mask<<<(N_NODES * MW / 4 + 255) / 256, 256>>>();
    k_scatter<<<(N_EDGES + 255) / 256, 256>>>(ei);
    k_degree<<<N_NODES / 8, 256>>>();

    __half *xh, *wh;
    cudaGetSymbolAddress((void**)&xh, g_xh);
    cudaGetSymbolAddress((void**)&wh, g_wh);

    int nx8 = N_NODES * D / 8;
    int nw8 = D * D / 8;
    k_cvt<<<(nx8 + 255) / 256, 256>>>((const float4*)x, (uint4*)xh, nx8);
    k_cvt<<<(nw8 + 255) / 256, 256>>>((const float4*)w, (uint4*)wh, nw8);

    dim3 gemmGrid(D / GBN, N_NODES / GBM);
    k_gemm_mma<<<gemmGrid, 256>>>();

    k_spmm<<<N_NODES, 128>>>(bias, out);
}

// round 7
// speedup vs baseline: 2.0591x; 1.0320x over previous
#include <cuda_runtime.h>
#include <cuda_fp16.h>
#include <cstdint>

#define N_NODES 8192
#define N_EDGES 262144
#define D 512
#define MW 256   // 8192 bits / 32 = 256 mask words per row

// Scratch (device globals; no allocations allowed)
__device__ unsigned int g_mask[N_NODES * MW];           // 8 MB adjacency bitmask
__device__ float        g_dinv[N_NODES];                // D^{-1/2}
__device__ __align__(16) __half g_h[N_NODES * D];       // H = X@W (UNscaled), fp16
__device__ int          g_is64;                         // edge_index dtype flag
__device__ __align__(16) __half g_xh[N_NODES * D];      // fp16 X
__device__ __align__(16) __half g_wh[D * D];            // fp16 W

// ---------------------------------------------------------------------------
// 0) detect edge_index dtype (int64 vs int32)
// ---------------------------------------------------------------------------
__global__ void k_detect(const int* __restrict__ ei32) {
    int t = threadIdx.x;
    int nz = 0;
    #pragma unroll
    for (int i = t; i < 4096; i += 256) nz |= ei32[2 * i + 1];
    int any = __syncthreads_or(nz != 0);
    if (t == 0) g_is64 = any ? 0 : 1;
}

// ---------------------------------------------------------------------------
// 1) zero bitmask (vectorized)
// ---------------------------------------------------------------------------
__global__ void k_zero_mask() {
    int i = blockIdx.x * blockDim.x + threadIdx.x;
    if (i < N_NODES * MW / 4) ((uint4*)g_mask)[i] = make_uint4(0, 0, 0, 0);
}

// ---------------------------------------------------------------------------
// 2) symmetric edge scatter into bitmask (dedup for free)
// ---------------------------------------------------------------------------
__global__ void k_scatter(const void* __restrict__ ei_raw) {
    int e = blockIdx.x * blockDim.x + threadIdx.x;
    if (e >= N_EDGES) return;
    int u, v;
    if (g_is64) {
        const long long* ei = (const long long*)ei_raw;
        u = (int)ei[e];
        v = (int)ei[N_EDGES + e];
    } else {
        const int* ei = (const int*)ei_raw;
        u = ei[e];
        v = ei[N_EDGES + e];
    }
    u &= (N_NODES - 1);
    v &= (N_NODES - 1);
    atomicOr(&g_mask[u * MW + (v >> 5)], 1u << (v & 31));
    atomicOr(&g_mask[v * MW + (u >> 5)], 1u << (u & 31));
}

// ---------------------------------------------------------------------------
// 3) degree + dinv: one warp per row. deg = popcount + 1 (identity)
// ---------------------------------------------------------------------------
__global__ void k_degree() {
    int row  = blockIdx.x * (blockDim.x >> 5) + (threadIdx.x >> 5);
    int lane = threadIdx.x & 31;
    if (row >= N_NODES) return;
    const uint4* m = (const uint4*)&g_mask[row * MW];
    int cnt = 0;
    #pragma unroll
    for (int w = 0; w < 2; w++) {
        uint4 q = m[lane + w * 32];
        cnt += __popc(q.x) + __popc(q.y) + __popc(q.z) + __popc(q.w);
    }
    #pragma unroll
    for (int o = 16; o; o >>= 1) cnt += __shfl_xor_sync(0xffffffffu, cnt, o);
    if (lane == 0) g_dinv[row] = rsqrtf((float)(cnt + 1));
}

// ---------------------------------------------------------------------------
// 3b) convert fp32 -> fp16 (8 floats / thread, one uint4 store)
// ---------------------------------------------------------------------------
__global__ void k_cvt(const float4* __restrict__ src, uint4* __restrict__ dst, int n8) {
    int i = blockIdx.x * blockDim.x + threadIdx.x;
    if (i >= n8) return;
    float4 a = src[2 * i];
    float4 b = src[2 * i + 1];
    uint4 o;
    __half2 h;
    h = __floats2half2_rn(a.x, a.y); o.x = *(uint32_t*)&h;
    h = __floats2half2_rn(a.z, a.w); o.y = *(uint32_t*)&h;
    h = __floats2half2_rn(b.x, b.y); o.z = *(uint32_t*)&h;
    h = __floats2half2_rn(b.z, b.w); o.w = *(uint32_t*)&h;
    dst[i] = o;
}

// ---------------------------------------------------------------------------
// 4) Tensor-core GEMM, single-pass fp16 (fp32 accumulate), NO dinv dependency:
//    H[m][n] = sum_k X[m][k]*W[k][n]   (stored fp16, unscaled)
// ---------------------------------------------------------------------------
#define GBM 128
#define GBN 128
#define GBK 32
#define ASTRIDE 40
#define BSTRIDE 144

__device__ __forceinline__ void ldsm_x4(uint32_t* r, const void* p) {
    uint32_t a = (uint32_t)__cvta_generic_to_shared(p);
    asm volatile("ldmatrix.sync.aligned.m8n8.x4.shared.b16 {%0,%1,%2,%3}, [%4];"
                 : "=r"(r[0]), "=r"(r[1]), "=r"(r[2]), "=r"(r[3]) : "r"(a));
}
__device__ __forceinline__ void ldsm_x4t(uint32_t* r, const void* p) {
    uint32_t a = (uint32_t)__cvta_generic_to_shared(p);
    asm volatile("ldmatrix.sync.aligned.m8n8.x4.trans.shared.b16 {%0,%1,%2,%3}, [%4];"
                 : "=r"(r[0]), "=r"(r[1]), "=r"(r[2]), "=r"(r[3]) : "r"(a));
}
__device__ __forceinline__ void mma16816(float* c, const uint32_t* a, const uint32_t* b) {
    asm volatile("mma.sync.aligned.m16n8k16.row.col.f32.f16.f16.f32 "
                 "{%0,%1,%2,%3}, {%4,%5,%6,%7}, {%8,%9}, {%0,%1,%2,%3};"
                 : "+f"(c[0]), "+f"(c[1]), "+f"(c[2]), "+f"(c[3])
                 : "r"(a[0]), "r"(a[1]), "r"(a[2]), "r"(a[3]), "r"(b[0]), "r"(b[1]));
}

__global__ __launch_bounds__(256) void k_gemm_mma() {
    __shared__ __half Ah[GBM * ASTRIDE];
    __shared__ __half Bh[GBK * BSTRIDE];

    int tid  = threadIdx.x;
    int lane = tid & 31;
    int wid  = tid >> 5;
    int wm   = wid & 1;
    int wn   = wid >> 1;
    int rowBase = blockIdx.y * GBM;
    int colBase = blockIdx.x * GBN;

    int ar = tid >> 2, ac = (tid & 3) * 8;
    int br = tid >> 4, bc = (tid & 15) * 8;

    float acc[4][4][4];
    #pragma unroll
    for (int mi = 0; mi < 4; mi++)
        #pragma unroll
        for (int ni = 0; ni < 4; ni++)
            #pragma unroll
            for (int q = 0; q < 4; q++) acc[mi][ni][q] = 0.0f;

    uint4 pA[2], pB[2];
    #pragma unroll
    for (int p = 0; p < 2; p++) {
        pA[p] = *(const uint4*)&g_xh[(rowBase + ar + p * 64) * D + ac];
        pB[p] = *(const uint4*)&g_wh[(br + p * 16) * D + colBase + bc];
    }

    for (int kt = 0; kt < D; kt += GBK) {
        __syncthreads();
        #pragma unroll
        for (int p = 0; p < 2; p++) {
            *(uint4*)&Ah[(ar + p * 64) * ASTRIDE + ac] = pA[p];
            *(uint4*)&Bh[(br + p * 16) * BSTRIDE + bc] = pB[p];
        }
        __syncthreads();

        if (kt + GBK < D) {
            int kn = kt + GBK;
            #pragma unroll
            for (int p = 0; p < 2; p++) {
                pA[p] = *(const uint4*)&g_xh[(rowBase + ar + p * 64) * D + kn + ac];
                pB[p] = *(const uint4*)&g_wh[(kn + br + p * 16) * D + colBase + bc];
            }
        }

        #pragma unroll
        for (int kk = 0; kk < GBK; kk += 16) {
            uint32_t af[4][4];
            #pragma unroll
            for (int mi = 0; mi < 4; mi++) {
                int r = wm * 64 + mi * 16 + (lane & 15);
                int c = kk + ((lane >> 4) << 3);
                ldsm_x4(af[mi], &Ah[r * ASTRIDE + c]);
            }
            uint32_t bf[4][2];
            #pragma unroll
            for (int np = 0; np < 2; np++) {
                int r = kk + (lane & 15);
                int c = wn * 32 + np * 16 + ((lane >> 4) << 3);
                uint32_t t4[4];
                ldsm_x4t(t4, &Bh[r * BSTRIDE + c]);
                bf[2 * np][0] = t4[0]; bf[2 * np][1] = t4[1];
                bf[2 * np + 1][0] = t4[2]; bf[2 * np + 1][1] = t4[3];
            }
            #pragma unroll
            for (int mi = 0; mi < 4; mi++)
                #pragma unroll
                for (int ni = 0; ni < 4; ni++)
                    mma16816(acc[mi][ni], af[mi], bf[ni]);
        }
    }

    // epilogue: write fp16 H (no scaling — dinv applied in SpMM)
    int g  = lane >> 2;
    int tg = lane & 3;
    #pragma unroll
    for (int mi = 0; mi < 4; mi++) {
        int row0 = rowBase + wm * 64 + mi * 16 + g;
        int row1 = row0 + 8;
        #pragma unroll
        for (int ni = 0; ni < 4; ni++) {
            int col = colBase + wn * 32 + ni * 8 + tg * 2;
            __half2 v0 = __floats2half2_rn(acc[mi][ni][0], acc[mi][ni][1]);
            __half2 v1 = __floats2half2_rn(acc[mi][ni][2], acc[mi][ni][3]);
            *(__half2*)&g_h[row0 * D + col] = v0;
            *(__half2*)&g_h[row1 * D + col] = v1;
        }
    }
}

// ---------------------------------------------------------------------------
// 5) SpMM gather (fp16 payload, 16B loads, per-neighbor dinv scaling):
//    out[i] = dinv_i*(sum_j dinv_j*H[j] + dinv_i*H[i]) + bias
//    dinv_i computed on the fly from the popcount total; dinv_j from g_dinv.
// ---------------------------------------------------------------------------
#define LIST_CAP 4096

__device__ __forceinline__ void fma_h8(float4& a, float4& b, uint4 u, float s) {
    float2 f;
    f = __half22float2(*(const __half2*)&u.x); a.x += s * f.x; a.y += s * f.y;
    f = __half22float2(*(const __half2*)&u.y); a.z += s * f.x; a.w += s * f.y;
    f = __half22float2(*(const __half2*)&u.z); b.x += s * f.x; b.y += s * f.y;
    f = __half22float2(*(const __half2*)&u.w); b.z += s * f.x; b.w += s * f.y;
}

__global__ __launch_bounds__(128) void k_spmm(const float* __restrict__ bias,
                                              float* __restrict__ out) {
    __shared__ unsigned int smask[MW];
    __shared__ unsigned short list[LIST_CAP];
    __shared__ int wsum[4];
    __shared__ __align__(16) float part[64 * 8];   // 2 KB combine buffer

    int row  = blockIdx.x;
    int tid  = threadIdx.x;
    int lane = tid & 31;
    int wrp  = tid >> 5;

    smask[tid]       = g_mask[row * MW + tid];
    smask[tid + 128] = g_mask[row * MW + tid + 128];
    __syncthreads();

    unsigned int w0 = smask[2 * tid], w1 = smask[2 * tid + 1];
    int c = __popc(w0) + __popc(w1);
    int p = c;
    #pragma unroll
    for (int o = 1; o < 32; o <<= 1) {
        int t = __shfl_up_sync(0xffffffffu, p, o);
        if (lane >= o) p += t;
    }
    if (lane == 31) wsum[wrp] = p;
    __syncthreads();
    int wbase = 0;
    #pragma unroll
    for (int w = 0; w < 4; w++) wbase += (w < wrp) ? wsum[w] : 0;
    int total = wsum[0] + wsum[1] + wsum[2] + wsum[3];

    float dinv_i = rsqrtf((float)(total + 1));   // == g_dinv[row]

    bool uselist = (total <= LIST_CAP);
    if (uselist) {
        int off = wbase + p - c;
        unsigned int bits = w0;
        int base = (2 * tid) << 5;
        while (bits) { int b = __ffs(bits) - 1; bits &= bits - 1; list[off++] = (unsigned short)(base + b); }
        bits = w1; base = (2 * tid + 1) << 5;
        while (bits) { int b = __ffs(bits) - 1; bits &= bits - 1; list[off++] = (unsigned short)(base + b); }
    }
    __syncthreads();

    int tid2 = tid & 63;
    int half = tid >> 6;

    const uint4* H4 = (const uint4*)g_h;

    float4 a0 = make_float4(0,0,0,0), b0 = make_float4(0,0,0,0);
    float4 a1 = make_float4(0,0,0,0), b1 = make_float4(0,0,0,0);
    float4 a2 = make_float4(0,0,0,0), b2 = make_float4(0,0,0,0);
    float4 a3 = make_float4(0,0,0,0), b3 = make_float4(0,0,0,0);

    if (half == 0) fma_h8(a0, b0, H4[row * 64 + tid2], dinv_i);   // identity term

    if (uselist) {
        int mid = total >> 1;
        int lo = half ? mid : 0;
        int hi = half ? total : mid;
        int i = lo;
        for (; i + 4 <= hi; i += 4) {
            int j0 = list[i], j1 = list[i + 1], j2 = list[i + 2], j3 = list[i + 3];
            float s0v = g_dinv[j0], s1v = g_dinv[j1], s2v = g_dinv[j2], s3v = g_dinv[j3];
            uint4 u0 = H4[j0 * 64 + tid2];
            uint4 u1 = H4[j1 * 64 + tid2];
            uint4 u2 = H4[j2 * 64 + tid2];
            uint4 u3 = H4[j3 * 64 + tid2];
            fma_h8(a0, b0, u0, s0v);
            fma_h8(a1, b1, u1, s1v);
            fma_h8(a2, b2, u2, s2v);
            fma_h8(a3, b3, u3, s3v);
        }
        for (; i < hi; i++) {
            int j = list[i];
            fma_h8(a0, b0, H4[j * 64 + tid2], g_dinv[j]);
        }
    } else {
        for (int w = half * 128; w < half * 128 + 128; w++) {
            unsigned int bits = smask[w];
            while (bits) {
                int b = __ffs(bits) - 1;
                bits &= bits - 1;
                int j = (w << 5) + b;
                fma_h8(a0, b0, H4[j * 64 + tid2], g_dinv[j]);
            }
        }
    }

    a0.x += a1.x + a2.x + a3.x;  a0.y += a1.y + a2.y + a3.y;
    a0.z += a1.z + a2.z + a3.z;  a0.w += a1.w + a2.w + a3.w;
    b0.x += b1.x + b2.x + b3.x;  b0.y += b1.y + b2.y + b3.y;
    b0.z += b1.z + b2.z + b3.z;  b0.w += b1.w + b2.w + b3.w;

    if (half == 1) {
        ((float4*)part)[tid2 * 2]     = a0;
        ((float4*)part)[tid2 * 2 + 1] = b0;
    }
    __syncthreads();
    if (half == 0) {
        float4 pa = ((float4*)part)[tid2 * 2];
        float4 pb = ((float4*)part)[tid2 * 2 + 1];
        a0.x += pa.x; a0.y += pa.y; a0.z += pa.z; a0.w += pa.w;
        b0.x += pb.x; b0.y += pb.y; b0.z += pb.z; b0.w += pb.w;

        float4 bia = ((const float4*)bias)[tid2 * 2];
        float4 bib = ((const float4*)bias)[tid2 * 2 + 1];
        float4 o0, o1;
        o0.x = dinv_i * a0.x + bia.x; o0.y = dinv_i * a0.y + bia.y;
        o0.z = dinv_i * a0.z + bia.z; o0.w = dinv_i * a0.w + bia.w;
        o1.x = dinv_i * b0.x + bib.x; o1.y = dinv_i * b0.y + bib.y;
        o1.z = dinv_i * b0.z + bib.z; o1.w = dinv_i * b0.w + bib.w;
        ((float4*)out)[row * (D / 4) + tid2 * 2]     = o0;
        ((float4*)out)[row * (D / 4) + tid2 * 2 + 1] = o1;
    }
}

// ---------------------------------------------------------------------------
// launch: fork graph-setup chain (stream 0) and cvt+GEMM chain (s2), join
// before SpMM. Streams/events created once on the first (uncaptured) call;
// no device memory is allocated.
// ---------------------------------------------------------------------------
extern "C" void kernel_launch(void* const* d_in, const int* in_sizes, int n_in,
                              void* d_out, int out_size) {
    const float* x    = (const float*)d_in[0];
    const void*  ei   = d_in[1];
    const float* w    = (const float*)d_in[2];
    const float* bias = (const float*)d_in[3];
    float*       out  = (float*)d_out;

    static cudaStream_t s2 = nullptr;
    static cudaEvent_t evFork = nullptr, evJoin = nullptr;
    if (s2 == nullptr) {
        cudaStreamCreateWithFlags(&s2, cudaStreamNonBlocking);
        cudaEventCreateWithFlags(&evFork, cudaEventDisableTiming);
        cudaEventCreateWithFlags(&evJoin, cudaEventDisableTiming);
    }

    __half *xh, *wh;
    cudaGetSymbolAddress((void**)&xh, g_xh);
    cudaGetSymbolAddress((void**)&wh, g_wh);
    int nx8 = N_NODES * D / 8;
    int nw8 = D * D / 8;

    // fork: side chain (cvt -> GEMM) on s2
    cudaEventRecord(evFork, 0);
    cudaStreamWaitEvent(s2, evFork, 0);
    k_cvt<<<(nx8 + 255) / 256, 256, 0, s2>>>((const float4*)x, (uint4*)xh, nx8);
    k_cvt<<<(nw8 + 255) / 256, 256, 0, s2>>>((const float4*)w, (uint4*)wh, nw8);
    dim3 gemmGrid(D / GBN, N_NODES / GBM);
    k_gemm_mma<<<gemmGrid, 256, 0, s2>>>();
    cudaEventRecord(evJoin, s2);

    // main chain: graph setup on stream 0
    k_detect<<<1, 256>>>((const int*)ei);
    k_zero_mask<<<(N_NODES * MW / 4 + 255) / 256, 256>>>();
    k_scatter<<<(N_EDGES + 255) / 256, 256>>>(ei);
    k_degree<<<N_NODES / 8, 256>>>();

    // join, then SpMM
    cudaStreamWaitEvent(0, evJoin, 0);
    k_spmm<<<N_NODES, 128>>>(bias, out);
}